// round 17
// baseline (speedup 1.0000x reference)
#include <cuda_runtime.h>
#include <cuda_fp16.h>
#include <cstdint>

#define FDIM 128
#define MAXN 50176   // 50000 rounded up to 128-row tiles
#define PAD  136     // smem row pitch in halves (LDSM conflict-free)
#define CAP  80      // bucket slots per source node (Poisson(32): P(>80) ~ 1e-11)
#define SPILLCAP 65536

// Scratch (allocation-free rule: __device__ globals)
__device__ __half   g_Wsh[FDIM * FDIM];           // Ws = W + W^T, fp16
__device__ __half   g_Gh[(size_t)MAXN * FDIM];    // G = X@Ws, fp16
__device__ __half   g_Xh[(size_t)MAXN * FDIM];    // X copy, fp16
__device__ int      g_idx64;                      // 1 if indices are int64
__device__ int      g_cnt[MAXN];                  // edges per source node
__device__ unsigned g_bucket[(size_t)MAXN * CAP]; // packed (m<<17)|j  (~16MB)
__device__ int      g_spillcnt;
__device__ uint4    g_spill[SPILLCAP];            // (i, j, m, -) overflow/odd edges

// ---------------------------------------------------------------------------
// Kernel 1 (fused prep): dtype detect (block 0) + Wsh + X->fp16 + cnt zeroing
// ---------------------------------------------------------------------------
__global__ __launch_bounds__(256)
void prep_kernel(const float* __restrict__ X, const float* __restrict__ W,
                 const void* __restrict__ mol, long long E,
                 long long nvec4, int N) {
    const int tid = threadIdx.x;
    long long t = (long long)blockIdx.x * 256 + tid;

    // dtype detect (validated R6: samples odd 32-bit words of first half)
    if (blockIdx.x == 0) {
        __shared__ int nonzero;
        if (tid == 0) nonzero = 0;
        __syncthreads();
        const int* p = (const int*)mol;
        long long half = E / 2;
        for (int s = tid; s < 1024; s += 256) {
            long long e = (half * s) / 1024;
            if (p[2 * e + 1] != 0) atomicExch(&nonzero, 1);
        }
        __syncthreads();
        if (tid == 0) {
            g_idx64 = (nonzero == 0) ? 1 : 0;
            g_spillcnt = 0;
        }
    }

    if (t < FDIM * FDIM) {
        int i = (int)(t >> 7), j = (int)(t & 127);
        g_Wsh[i * FDIM + j] = __float2half_rn(W[i * FDIM + j] + W[j * FDIM + i]);
    }
    if (t < nvec4) {
        float4 v = ((const float4*)X)[t];
        __half2 h0 = __floats2half2_rn(v.x, v.y);
        __half2 h1 = __floats2half2_rn(v.z, v.w);
        uint2 o;
        o.x = *(unsigned*)&h0;
        o.y = *(unsigned*)&h1;
        ((uint2*)g_Xh)[t] = o;
    }
    if (t < N) g_cnt[t] = 0;
}

// ---------------------------------------------------------------------------
// Kernel 2: G = Xh @ Wsh via HMMA mma.sync.m16n8k16 (fp16 in, fp32 accum).
// ---------------------------------------------------------------------------
__device__ __forceinline__ void ldsm_x4(uint32_t addr, unsigned& r0, unsigned& r1,
                                        unsigned& r2, unsigned& r3) {
    asm volatile("ldmatrix.sync.aligned.m8n8.x4.shared.b16 {%0,%1,%2,%3}, [%4];"
                 : "=r"(r0), "=r"(r1), "=r"(r2), "=r"(r3) : "r"(addr));
}

__device__ __forceinline__ void ldsm_x4_t(uint32_t addr, unsigned& r0, unsigned& r1,
                                          unsigned& r2, unsigned& r3) {
    asm volatile("ldmatrix.sync.aligned.m8n8.x4.trans.shared.b16 {%0,%1,%2,%3}, [%4];"
                 : "=r"(r0), "=r"(r1), "=r"(r2), "=r"(r3) : "r"(addr));
}

__device__ __forceinline__ void mma16816(float* c, unsigned a0, unsigned a1,
                                         unsigned a2, unsigned a3,
                                         unsigned b0, unsigned b1) {
    asm volatile(
        "mma.sync.aligned.m16n8k16.row.col.f32.f16.f16.f32 "
        "{%0,%1,%2,%3}, {%4,%5,%6,%7}, {%8,%9}, {%0,%1,%2,%3};"
        : "+f"(c[0]), "+f"(c[1]), "+f"(c[2]), "+f"(c[3])
        : "r"(a0), "r"(a1), "r"(a2), "r"(a3), "r"(b0), "r"(b1));
}

__global__ __launch_bounds__(256) void gemm_kernel(int N) {
    extern __shared__ __align__(16) __half smem[];
    __half* Xs  = smem;                 // 128 x PAD
    __half* Wss = smem + 128 * PAD;     // 128 x PAD

    const int tid  = threadIdx.x;
    const int row0 = blockIdx.x * 128;

    for (int t = tid; t < 128 * 16; t += 256) {
        int r = t >> 4, c = t & 15;
        *(uint4*)&Wss[r * PAD + c * 8] = ((const uint4*)g_Wsh)[r * 16 + c];
    }
    for (int t = tid; t < 128 * 16; t += 256) {
        int r = t >> 4, c = t & 15;
        int gr = row0 + r;
        uint4 v = (gr < N) ? ((const uint4*)g_Xh)[(size_t)gr * 16 + c]
                           : make_uint4(0u, 0u, 0u, 0u);
        *(uint4*)&Xs[r * PAD + c * 8] = v;
    }
    __syncthreads();

    const int warp = tid >> 5;
    const int lane = tid & 31;
    const int wrow = warp * 16;
    const int g    = lane >> 3;

    const int aRow  = wrow + (lane & 7) + ((g & 1) ? 8 : 0);
    const int aKoff = (g >= 2) ? 8 : 0;
    const int bK    = (lane & 7) + ((g & 1) ? 8 : 0);
    const int bNoff = (g >= 2) ? 8 : 0;

    const uint32_t xsBase = (uint32_t)__cvta_generic_to_shared(Xs);
    const uint32_t wsBase = (uint32_t)__cvta_generic_to_shared(Wss);

    float c[16][4];
#pragma unroll
    for (int n = 0; n < 16; n++)
#pragma unroll
        for (int q = 0; q < 4; q++) c[n][q] = 0.f;

#pragma unroll
    for (int k0 = 0; k0 < 128; k0 += 16) {
        unsigned a0, a1, a2, a3;
        ldsm_x4(xsBase + (uint32_t)(aRow * PAD + k0 + aKoff) * 2, a0, a1, a2, a3);
#pragma unroll
        for (int nt = 0; nt < 16; nt += 2) {
            unsigned b0, b1, b2, b3;
            ldsm_x4_t(wsBase + (uint32_t)((bK + k0) * PAD + nt * 8 + bNoff) * 2,
                      b0, b1, b2, b3);
            mma16816(c[nt],     a0, a1, a2, a3, b0, b1);
            mma16816(c[nt + 1], a0, a1, a2, a3, b2, b3);
        }
    }

    const int erow = wrow + (lane >> 2);
    const int ecol4 = lane & 3;
#pragma unroll
    for (int nt = 0; nt < 16; nt++) {
        int colh = nt * 4 + ecol4;
        int gr0 = row0 + erow;
        int gr1 = gr0 + 8;
        if (gr0 < N) {
            __half2 h = __floats2half2_rn(c[nt][0], c[nt][1]);
            ((unsigned*)g_Gh)[(size_t)gr0 * 64 + colh] = *(unsigned*)&h;
        }
        if (gr1 < N) {
            __half2 h = __floats2half2_rn(c[nt][2], c[nt][3]);
            ((unsigned*)g_Gh)[(size_t)gr1 * 64 + colh] = *(unsigned*)&h;
        }
    }
}

// ---------------------------------------------------------------------------
// Kernel 3: scatter edges into per-source buckets (packed 4B entries).
// ---------------------------------------------------------------------------
__device__ __forceinline__ void scatter_one(int i, int j, int m) {
    int pos = atomicAdd(&g_cnt[i], 1);
    if (pos < CAP && (unsigned)j < (1u << 17) && (unsigned)m < (1u << 15)) {
        g_bucket[(size_t)i * CAP + pos] = (unsigned)j | ((unsigned)m << 17);
    } else {
        int sp = atomicAdd(&g_spillcnt, 1);
        if (sp < SPILLCAP)
            g_spill[sp] = make_uint4((unsigned)i, (unsigned)j, (unsigned)m, 0u);
    }
}

__global__ __launch_bounds__(256)
void scatter_kernel(const void* __restrict__ nbr,
                    const void* __restrict__ mol, long long E) {
    long long stride4 = (long long)gridDim.x * blockDim.x * 4;
    long long e0 = ((long long)blockIdx.x * blockDim.x + threadIdx.x) * 4;

    if (g_idx64 == 0) {
        const int* __restrict__ src = (const int*)nbr;
        const int* __restrict__ dst = src + E;
        const int* __restrict__ mm  = (const int*)mol;
        for (; e0 < E; e0 += stride4) {
            if (e0 + 4 <= E) {
                int4 si = *(const int4*)(src + e0);
                int4 sj = *(const int4*)(dst + e0);
                int4 sm = *(const int4*)(mm + e0);
                scatter_one(si.x, sj.x, sm.x);
                scatter_one(si.y, sj.y, sm.y);
                scatter_one(si.z, sj.z, sm.z);
                scatter_one(si.w, sj.w, sm.w);
            } else {
                for (long long e = e0; e < E; e++)
                    scatter_one(src[e], dst[e], mm[e]);
            }
        }
    } else {
        const long long* __restrict__ src = (const long long*)nbr;
        const long long* __restrict__ dst = src + E;
        const long long* __restrict__ mm  = (const long long*)mol;
        for (; e0 < E; e0 += stride4) {
            long long hi = e0 + 4 < E ? e0 + 4 : E;
            for (long long e = e0; e < hi; e++)
                scatter_one((int)src[e], (int)dst[e], (int)mm[e]);
        }
    }
}

// ---------------------------------------------------------------------------
// Kernel 4: process — warp per source row, THREAD per edge.
// Lanes 0-15 stage G[i] into smem as fp32 (once per row, broadcast reads).
// Each lane owns one bucket edge: 16 LDG.128 chunks of X[j] (unroll x4,
// 4 loads in flight), fp32 dot vs broadcast LDS of G, one smem atomic.
// No shuffles, no reductions. Tail: block flush + spill edges.
// ---------------------------------------------------------------------------
__device__ __forceinline__ float chunk_dot(uint4 x, const float* g) {
    float2 b0 = __half22float2(*(const __half2*)&x.x);
    float2 b1 = __half22float2(*(const __half2*)&x.y);
    float2 b2 = __half22float2(*(const __half2*)&x.z);
    float2 b3 = __half22float2(*(const __half2*)&x.w);
    float s = b0.x * g[0];
    s = fmaf(b0.y, g[1], s);
    s = fmaf(b1.x, g[2], s);
    s = fmaf(b1.y, g[3], s);
    s = fmaf(b2.x, g[4], s);
    s = fmaf(b2.y, g[5], s);
    s = fmaf(b3.x, g[6], s);
    s = fmaf(b3.y, g[7], s);
    return s;
}

__device__ __forceinline__ float hdot8(uint4 ua, uint4 ub) {
    float2 a0 = __half22float2(*(const __half2*)&ua.x);
    float2 a1 = __half22float2(*(const __half2*)&ua.y);
    float2 a2 = __half22float2(*(const __half2*)&ua.z);
    float2 a3 = __half22float2(*(const __half2*)&ua.w);
    float2 b0 = __half22float2(*(const __half2*)&ub.x);
    float2 b1 = __half22float2(*(const __half2*)&ub.y);
    float2 b2 = __half22float2(*(const __half2*)&ub.z);
    float2 b3 = __half22float2(*(const __half2*)&ub.w);
    float s = a0.x * b0.x;
    s = fmaf(a0.y, b0.y, s);
    s = fmaf(a1.x, b1.x, s);
    s = fmaf(a1.y, b1.y, s);
    s = fmaf(a2.x, b2.x, s);
    s = fmaf(a2.y, b2.y, s);
    s = fmaf(a3.x, b3.x, s);
    s = fmaf(a3.y, b3.y, s);
    return s;
}

__global__ __launch_bounds__(256)
void process_kernel(int N, float* __restrict__ out, int M) {
    extern __shared__ float sm[];
    float* acc = sm;          // [M]
    float* gf  = sm + M;      // [8 warps][128] fp32 G row

    for (int t = threadIdx.x; t < M; t += blockDim.x) acc[t] = 0.f;
    __syncthreads();

    const int warp = threadIdx.x >> 5;
    const int lane = threadIdx.x & 31;
    float* gw = gf + warp * FDIM;
    const uint4* __restrict__ B = (const uint4*)g_Xh;

    long long wr = (long long)blockIdx.x * 8 + warp;
    long long nw = (long long)gridDim.x * 8;

    for (long long r = wr; r < N; r += nw) {
        int cnt = g_cnt[r];
        if (cnt > CAP) cnt = CAP;
        if (cnt == 0) continue;

        // Stage G[r] into smem as fp32 (lanes 0-15, chunk = lane)
        if (lane < 16) {
            uint4 gv = ((const uint4*)g_Gh)[(size_t)r * 16 + lane];
            float2 f0 = __half22float2(*(const __half2*)&gv.x);
            float2 f1 = __half22float2(*(const __half2*)&gv.y);
            float2 f2 = __half22float2(*(const __half2*)&gv.z);
            float2 f3 = __half22float2(*(const __half2*)&gv.w);
            float4 o0 = make_float4(f0.x, f0.y, f1.x, f1.y);
            float4 o1 = make_float4(f2.x, f2.y, f3.x, f3.y);
            *(float4*)&gw[lane * 8 + 0] = o0;
            *(float4*)&gw[lane * 8 + 4] = o1;
        }
        __syncwarp();

        const unsigned* __restrict__ bk = g_bucket + (size_t)r * CAP;
        for (int base = 0; base < cnt; base += 32) {
            int ei = base + lane;
            bool act = ei < cnt;
            unsigned v = act ? bk[ei] : 0u;
            int j = (int)(v & 0x1FFFFu);
            int m = (int)(v >> 17);

            float s = 0.f;
            const uint4* xr = B + (size_t)j * 16;
#pragma unroll
            for (int c = 0; c < 16; c += 4) {
                uint4 x0, x1, x2, x3;
                if (act) {
                    x0 = xr[c + 0];
                    x1 = xr[c + 1];
                    x2 = xr[c + 2];
                    x3 = xr[c + 3];
                    s += chunk_dot(x0, gw + (c + 0) * 8);
                    s += chunk_dot(x1, gw + (c + 1) * 8);
                    s += chunk_dot(x2, gw + (c + 2) * 8);
                    s += chunk_dot(x3, gw + (c + 3) * 8);
                }
            }
            if (act) atomicAdd(&acc[m], s);
        }
        __syncwarp();   // gw reused next row
    }

    __syncthreads();
    for (int t = threadIdx.x; t < M; t += blockDim.x)
        atomicAdd(&out[t], acc[t]);

    // Spill edges (bucket overflow / out-of-range) — normally zero.
    int ns = g_spillcnt;
    if (ns > SPILLCAP) ns = SPILLCAP;
    const uint4* __restrict__ A = (const uint4*)g_Gh;
    for (int e = blockIdx.x * blockDim.x + threadIdx.x; e < ns;
         e += gridDim.x * blockDim.x) {
        uint4 ent = g_spill[e];
        float s = 0.f;
#pragma unroll
        for (int c = 0; c < 16; c++)
            s += hdot8(A[(size_t)ent.x * 16 + c], B[(size_t)ent.y * 16 + c]);
        atomicAdd(&out[ent.z], s);
    }
}

// ---------------------------------------------------------------------------
// Launch (5 launches total incl. memset)
// ---------------------------------------------------------------------------
extern "C" void kernel_launch(void* const* d_in, const int* in_sizes, int n_in,
                              void* d_out, int out_size) {
    const float* X  = (const float*)d_in[0];   // [N, 128] fp32
    const float* W  = (const float*)d_in[1];   // [128, 128] fp32
    const void*  nbr = d_in[2];                // [2, E] int32 (detected) or int64
    const void*  mol = d_in[3];                // [E]
    float* out = (float*)d_out;                // [M] fp32

    const long long E = (long long)in_sizes[3];
    const int N = in_sizes[0] / FDIM;

    cudaMemsetAsync(d_out, 0, (size_t)out_size * sizeof(float), 0);

    long long nvec4 = (long long)N * FDIM / 4;
    int prep_blocks = (int)((nvec4 + 255) / 256);
    prep_kernel<<<prep_blocks, 256>>>(X, W, mol, E, nvec4, N);

    size_t gemm_smem = (size_t)2 * 128 * PAD * sizeof(__half);
    cudaFuncSetAttribute(gemm_kernel, cudaFuncAttributeMaxDynamicSharedMemorySize,
                         (int)gemm_smem);
    int gemm_blocks = (N + 127) / 128;
    gemm_kernel<<<gemm_blocks, 256, gemm_smem>>>(N);

    scatter_kernel<<<1184, 256>>>(nbr, mol, E);

    size_t psmem = ((size_t)out_size + 8 * FDIM) * sizeof(float);
    process_kernel<<<592, 256, psmem>>>(N, out, out_size);
}